// round 1
// baseline (speedup 1.0000x reference)
#include <cuda_runtime.h>

// ---------------------------------------------------------------------------
// SpanClassifier: two single-head relative-position attention logit maps.
//   B=8, S=2048, D=256, K_rel=64 (NREL = 2K+1 = 129)
// Pipeline:
//   1) proj_kernel   : Q1,K1,Q2,K2 = X@Wᵀ + b  (Q scaled by 1/sqrt(D)=1/16)
//   2) qr_kernel     : QR_h = Q_h @ rel_hᵀ   [16384, 129] (stride-padded to 132)
//   3) scores_kernel : out = Q@Kᵀ + QR gather(clip(k-q)) with mask, per (head,b)
// All fp32. Scratch in __device__ globals (no allocation).
// ---------------------------------------------------------------------------

namespace {
constexpr int B_   = 8;
constexpr int S_   = 2048;
constexpr int D_   = 256;
constexpr int NREL = 129;   // 2*64 + 1
constexpr int QRS  = 132;   // padded row stride for QR
constexpr int BS_  = B_ * S_;   // 16384

constexpr int BM = 128, BN = 128, BK = 16, TM = 8, TN = 8;
}

// Scratch: Q1,K1,Q2,K2 (64 MB) and QR1,QR2 (~17 MB)
__device__ float g_P[4][BS_ * D_];
__device__ float g_QR[2][BS_ * QRS];

// ---------------------------------------------------------------------------
// Shared SGEMM core: C_tile[BM,BN] = A[BM,256] * B[validN,256]^T
// A, Bm point at tile origins; both row-major with leading dim 256.
// ---------------------------------------------------------------------------
__device__ __forceinline__ void sgemm_tile(
    const float* __restrict__ A, const float* __restrict__ Bm,
    int validN, float acc[TM][TN])
{
    __shared__ float As[BK][BM];
    __shared__ float Bs[BK][BN];

    const int tid     = threadIdx.x;
    const int rowBase = (tid >> 4) * TM;
    const int colBase = (tid & 15) * TN;
    const int lr      = tid >> 2;        // 0..63
    const int lc      = (tid & 3) * 4;   // 0,4,8,12

#pragma unroll
    for (int i = 0; i < TM; i++)
#pragma unroll
        for (int j = 0; j < TN; j++) acc[i][j] = 0.f;

    for (int k0 = 0; k0 < D_; k0 += BK) {
#pragma unroll
        for (int p = 0; p < 2; p++) {
            const int r = lr + p * 64;
            float4 av = *(const float4*)(A + (size_t)r * D_ + k0 + lc);
            As[lc + 0][r] = av.x;
            As[lc + 1][r] = av.y;
            As[lc + 2][r] = av.z;
            As[lc + 3][r] = av.w;
            float4 bv = make_float4(0.f, 0.f, 0.f, 0.f);
            if (r < validN)
                bv = *(const float4*)(Bm + (size_t)r * D_ + k0 + lc);
            Bs[lc + 0][r] = bv.x;
            Bs[lc + 1][r] = bv.y;
            Bs[lc + 2][r] = bv.z;
            Bs[lc + 3][r] = bv.w;
        }
        __syncthreads();

#pragma unroll
        for (int kk = 0; kk < BK; kk++) {
            float a[TM], b[TN];
            *(float4*)&a[0] = *(const float4*)&As[kk][rowBase];
            *(float4*)&a[4] = *(const float4*)&As[kk][rowBase + 4];
            *(float4*)&b[0] = *(const float4*)&Bs[kk][colBase];
            *(float4*)&b[4] = *(const float4*)&Bs[kk][colBase + 4];
#pragma unroll
            for (int i = 0; i < TM; i++)
#pragma unroll
                for (int j = 0; j < TN; j++)
                    acc[i][j] += a[i] * b[j];
        }
        __syncthreads();
    }
}

// ---------------------------------------------------------------------------
// 1) Projections: z in {0:Q1, 1:K1, 2:Q2, 3:K2}
// ---------------------------------------------------------------------------
__global__ void __launch_bounds__(256, 2)
proj_kernel(const float* __restrict__ X,
            const float* __restrict__ W0, const float* __restrict__ b0,
            const float* __restrict__ W1, const float* __restrict__ b1,
            const float* __restrict__ W2, const float* __restrict__ b2,
            const float* __restrict__ W3, const float* __restrict__ b3)
{
    const int z = blockIdx.z;
    const float* W    = (z == 0) ? W0 : (z == 1) ? W1 : (z == 2) ? W2 : W3;
    const float* bias = (z == 0) ? b0 : (z == 1) ? b1 : (z == 2) ? b2 : b3;
    const float scale = (z == 0 || z == 2) ? 0.0625f : 1.0f;  // 1/sqrt(256)
    float* dst = g_P[z];

    const int mBase = blockIdx.y * BM;
    const int nBase = blockIdx.x * BN;

    float acc[TM][TN];
    sgemm_tile(X + (size_t)mBase * D_, W + (size_t)nBase * D_, BN, acc);

    const int tid     = threadIdx.x;
    const int rowBase = (tid >> 4) * TM;
    const int colBase = (tid & 15) * TN;

    float bb[TN];
#pragma unroll
    for (int j = 0; j < TN; j++) bb[j] = bias[nBase + colBase + j];

#pragma unroll
    for (int i = 0; i < TM; i++) {
        const int m = mBase + rowBase + i;
        float vals[TN];
#pragma unroll
        for (int j = 0; j < TN; j++) vals[j] = (acc[i][j] + bb[j]) * scale;
        float* orow = dst + (size_t)m * D_ + nBase + colBase;
        *(float4*)&orow[0] = *(float4*)&vals[0];
        *(float4*)&orow[4] = *(float4*)&vals[4];
    }
}

// ---------------------------------------------------------------------------
// 2) QR_h[m, r] = Q_h[m,:] . rel_h[r,:]   (r < 129, stored with stride 132)
// ---------------------------------------------------------------------------
__global__ void __launch_bounds__(256, 2)
qr_kernel(const float* __restrict__ rel1, const float* __restrict__ rel2)
{
    const int head = blockIdx.z;
    const float* rel = (head == 0) ? rel1 : rel2;
    const float* Q   = g_P[head * 2];
    float* dst       = g_QR[head];

    const int mBase  = blockIdx.y * BM;
    const int nBase  = blockIdx.x * BN;
    const int validN = min(BN, NREL - nBase);

    float acc[TM][TN];
    sgemm_tile(Q + (size_t)mBase * D_, rel + (size_t)nBase * D_, validN, acc);

    const int tid     = threadIdx.x;
    const int rowBase = (tid >> 4) * TM;
    const int colBase = (tid & 15) * TN;

#pragma unroll
    for (int i = 0; i < TM; i++) {
        const int m = mBase + rowBase + i;
#pragma unroll
        for (int j = 0; j < TN; j++) {
            const int n = nBase + colBase + j;
            if (n < NREL) dst[(size_t)m * QRS + n] = acc[i][j];
        }
    }
}

// ---------------------------------------------------------------------------
// 3) Scores: out[head,b,q,k] = Q.K^T + QR[q, clip(k-q,-64,64)+64], masked
//    blockIdx.z = head*8 + b
// ---------------------------------------------------------------------------
__global__ void __launch_bounds__(256, 2)
scores_kernel(const int* __restrict__ mask, float* __restrict__ out)
{
    const int z    = blockIdx.z;
    const int head = z >> 3;
    const int b    = z & 7;

    const float* Q  = g_P[head * 2 + 0] + (size_t)b * S_ * D_;
    const float* Km = g_P[head * 2 + 1] + (size_t)b * S_ * D_;
    const float* QR = g_QR[head] + (size_t)b * S_ * QRS;
    const int* mrow = mask + b * S_;
    float* o = out + ((size_t)head * B_ + b) * (size_t)S_ * S_;

    const int qBase = blockIdx.y * BM;
    const int kBase = blockIdx.x * BN;

    float acc[TM][TN];
    sgemm_tile(Q + (size_t)qBase * D_, Km + (size_t)kBase * D_, BN, acc);

    const int tid     = threadIdx.x;
    const int rowBase = (tid >> 4) * TM;
    const int colBase = (tid & 15) * TN;

    int mk[TN];
#pragma unroll
    for (int j = 0; j < TN; j++) mk[j] = mrow[kBase + colBase + j];

#pragma unroll
    for (int i = 0; i < TM; i++) {
        const int qg = qBase + rowBase + i;
        const int mq = mrow[qg];
        const float* qr = QR + (size_t)qg * QRS;
        float vals[TN];
#pragma unroll
        for (int j = 0; j < TN; j++) {
            const int kg = kBase + colBase + j;
            int d = kg - qg;
            d = (d < -64) ? -64 : ((d > 64) ? 64 : d);
            float v = acc[i][j] + qr[d + 64];
            if (mq == 0 || mk[j] == 0) v = -1e18f;
            vals[j] = v;
        }
        float* orow = o + (size_t)qg * S_ + kBase + colBase;
        *(float4*)&orow[0] = *(float4*)&vals[0];
        *(float4*)&orow[4] = *(float4*)&vals[4];
    }
}

// ---------------------------------------------------------------------------
// Launch. Inputs (metadata order):
//  0 repre, 1 mask, 2 wq1, 3 bq1, 4 wk1, 5 bk1, 6 rel1,
//  7 wq2, 8 bq2, 9 wk2, 10 bk2, 11 rel2
// Output: concat(span_st_logits, span_ed_logits) -> 2*B*S*S f32
// ---------------------------------------------------------------------------
extern "C" void kernel_launch(void* const* d_in, const int* in_sizes, int n_in,
                              void* d_out, int out_size)
{
    const float* repre = (const float*)d_in[0];
    const int*   mask  = (const int*)d_in[1];
    const float* wq1 = (const float*)d_in[2];
    const float* bq1 = (const float*)d_in[3];
    const float* wk1 = (const float*)d_in[4];
    const float* bk1 = (const float*)d_in[5];
    const float* rel1 = (const float*)d_in[6];
    const float* wq2 = (const float*)d_in[7];
    const float* bq2 = (const float*)d_in[8];
    const float* wk2 = (const float*)d_in[9];
    const float* bk2 = (const float*)d_in[10];
    const float* rel2 = (const float*)d_in[11];
    float* out = (float*)d_out;

    (void)in_sizes; (void)n_in; (void)out_size;

    // 1) projections: grid (N tiles=2, M tiles=128, z=4 matrices)
    proj_kernel<<<dim3(D_ / BN, BS_ / BM, 4), 256>>>(
        repre, wq1, bq1, wk1, bk1, wq2, bq2, wk2, bk2);

    // 2) q_rel: grid (ceil(129/128)=2, 128, heads=2)
    qr_kernel<<<dim3((NREL + BN - 1) / BN, BS_ / BM, 2), 256>>>(rel1, rel2);

    // 3) scores: grid (k tiles=16, q tiles=16, head*8+b = 16)
    scores_kernel<<<dim3(S_ / BN, S_ / BM, 16), 256>>>(mask, out);
}

// round 3
// speedup vs baseline: 2.3683x; 2.3683x over previous
#include <cuda_runtime.h>
#include <cuda_bf16.h>
#include <cstdint>

// ---------------------------------------------------------------------------
// SpanClassifier via portable mma.sync bf16x3 (split-fp32) GEMMs.
//   B=8, S=2048, D=256, NREL=129
// tcgen05 is rejected by this toolchain (compute_103 virtual arch), so we use
// baseline-PTX ldmatrix + mma.sync.m16n8k16 (legacy HMMA tensor pipe).
//
// Pipeline:
//   0) convert:  f32 -> (hi,lo) bf16 pairs for X, W1..4, rel1..2
//   1) proj:     Q1,K1,Q2,K2 = X@W^T + b (Q scaled 1/16) -> bf16 hi/lo
//   2) qr:       QR_h = Q_h @ rel_h^T -> f32 [16384,129] (stride 132)
//   3) scores:   out = Q@K^T + QR gather(clip(k-q)) + mask
// GEMM tile: 128x128, K=256 in 4 chunks of 64. Per chunk per k16-step:
// 3 MMAs (hi*hi, hi*lo, lo*hi), fp32 accumulate in registers.
// ---------------------------------------------------------------------------

namespace {
constexpr int B_   = 8;
constexpr int S_   = 2048;
constexpr int D_   = 256;
constexpr int NREL = 129;
constexpr int QRS  = 132;
constexpr int BS_  = B_ * S_;   // 16384

constexpr int STRB   = 144;            // smem row stride in BYTES (64 bf16 + 8 pad)
constexpr int TILE_B = 128 * STRB;     // 18432 bytes per tile
constexpr int SM_AHI = 0;
constexpr int SM_ALO = TILE_B;
constexpr int SM_BHI = 2 * TILE_B;
constexpr int SM_BLO = 3 * TILE_B;
constexpr int SMEM_DYN = 4 * TILE_B;   // 73728 bytes
}

// ---------------- scratch (device globals; no runtime allocation) ----------
__device__ __nv_bfloat16 g_Xhi[BS_ * D_];
__device__ __nv_bfloat16 g_Xlo[BS_ * D_];
__device__ __nv_bfloat16 g_Phi[4][BS_ * D_];
__device__ __nv_bfloat16 g_Plo[4][BS_ * D_];
__device__ __nv_bfloat16 g_Whi[4][D_ * D_];
__device__ __nv_bfloat16 g_Wlo[4][D_ * D_];
__device__ __nv_bfloat16 g_Rhi[2][NREL * D_];
__device__ __nv_bfloat16 g_Rlo[2][NREL * D_];
__device__ float g_QR[2][BS_ * QRS];

// ---------------- PTX helpers ----------------------------------------------
__device__ __forceinline__ uint32_t smem_u32(const void* p) {
    uint32_t a;
    asm("{ .reg .u64 t; cvta.to.shared.u64 t, %1; cvt.u32.u64 %0, t; }"
        : "=r"(a) : "l"(p));
    return a;
}

#define LDSM4(R, addr)                                                        \
    asm volatile("ldmatrix.sync.aligned.m8n8.x4.shared.b16 {%0,%1,%2,%3}, [%4];" \
                 : "=r"((R)[0]), "=r"((R)[1]), "=r"((R)[2]), "=r"((R)[3])     \
                 : "r"(addr))

#define MMA_BF16(C, A, B0, B1)                                                \
    asm volatile("mma.sync.aligned.m16n8k16.row.col.f32.bf16.bf16.f32 "       \
                 "{%0,%1,%2,%3},{%4,%5,%6,%7},{%8,%9},{%0,%1,%2,%3};"         \
                 : "+f"((C)[0]), "+f"((C)[1]), "+f"((C)[2]), "+f"((C)[3])     \
                 : "r"((A)[0]), "r"((A)[1]), "r"((A)[2]), "r"((A)[3]),        \
                   "r"(B0), "r"(B1))

#define STS128(addr, v)                                                       \
    asm volatile("st.shared.v4.b32 [%0], {%1,%2,%3,%4};"                      \
                 :: "r"(addr), "r"((v).x), "r"((v).y), "r"((v).z), "r"((v).w))

// ---------------- tile loader: GMEM bf16 [*,256] -> padded SMEM ------------
// Loads rows [row0, row0+128) cols [col0, col0+64) into tile at smbase.
__device__ __forceinline__ void load_tile(uint32_t smbase,
                                          const __nv_bfloat16* __restrict__ src,
                                          int row0, int col0, int rowLim, int tid)
{
#pragma unroll
    for (int it = 0; it < 4; it++) {
        int idx = it * 256 + tid;     // 0..1023
        int r   = idx >> 3;           // 0..127
        int c8  = idx & 7;            // 8 bf16 each
        uint4 v = make_uint4(0, 0, 0, 0);
        int gr = row0 + r;
        if (gr < rowLim)
            v = *(const uint4*)(src + (size_t)gr * D_ + col0 + c8 * 8);
        uint32_t a = smbase + (uint32_t)(r * STRB + c8 * 16);
        STS128(a, v);
    }
}

// ---------------- GEMM core: acc[2][8][4] = A[128,256] * B^T ---------------
// Warp grid 4x2 (m x n): warp computes 32x64 via 2x8 m16n8k16 tiles.
extern __shared__ char dynsm[];

__device__ __forceinline__ void gemm_mma(
    const __nv_bfloat16* __restrict__ Ahi, const __nv_bfloat16* __restrict__ Alo,
    const __nv_bfloat16* __restrict__ Bhi, const __nv_bfloat16* __restrict__ Blo,
    int rowA0, int rowB0, int bLim, float acc[2][8][4])
{
    const int tid  = threadIdx.x;
    const int lane = tid & 31;
    const int wid  = tid >> 5;
    const int mw   = wid >> 1;   // 0..3
    const int nw   = wid & 1;    // 0..1

    const uint32_t smb = smem_u32(dynsm);

    // ldmatrix lane addressing: row = lane&15 within 16-row group,
    // k-half byte offset = (lane>>4)*16.
    const int lrow       = lane & 15;
    const uint32_t khalf = (uint32_t)((lane >> 4) * 16);

    const uint32_t aHi = smb + SM_AHI + (uint32_t)((mw * 32 + lrow) * STRB) + khalf;
    const uint32_t aLo = aHi + (SM_ALO - SM_AHI);
    const uint32_t bHi = smb + SM_BHI + (uint32_t)((nw * 64 + lrow) * STRB) + khalf;
    const uint32_t bLo = bHi + (SM_BLO - SM_BHI);

#pragma unroll
    for (int mt = 0; mt < 2; mt++)
#pragma unroll
        for (int nt = 0; nt < 8; nt++)
#pragma unroll
            for (int e = 0; e < 4; e++) acc[mt][nt][e] = 0.f;

    for (int c = 0; c < 4; c++) {
        const int col0 = c * 64;
        load_tile(smb + SM_AHI, Ahi, rowA0, col0, 1 << 30, tid);
        load_tile(smb + SM_ALO, Alo, rowA0, col0, 1 << 30, tid);
        load_tile(smb + SM_BHI, Bhi, rowB0, col0, bLim, tid);
        load_tile(smb + SM_BLO, Blo, rowB0, col0, bLim, tid);
        __syncthreads();

#pragma unroll
        for (int ks = 0; ks < 4; ks++) {
            const uint32_t ko = (uint32_t)(ks * 32);
            uint32_t ah[2][4], al[2][4];
#pragma unroll
            for (int mt = 0; mt < 2; mt++) {
                LDSM4(ah[mt], aHi + (uint32_t)(mt * 16 * STRB) + ko);
                LDSM4(al[mt], aLo + (uint32_t)(mt * 16 * STRB) + ko);
            }
#pragma unroll
            for (int ntp = 0; ntp < 4; ntp++) {
                uint32_t bh[4], bl[4];
                LDSM4(bh, bHi + (uint32_t)(ntp * 16 * STRB) + ko);
                LDSM4(bl, bLo + (uint32_t)(ntp * 16 * STRB) + ko);
                const int nt0 = ntp * 2, nt1 = nt0 + 1;
#pragma unroll
                for (int mt = 0; mt < 2; mt++) {
                    MMA_BF16(acc[mt][nt0], ah[mt], bh[0], bh[2]);
                    MMA_BF16(acc[mt][nt0], ah[mt], bl[0], bl[2]);
                    MMA_BF16(acc[mt][nt0], al[mt], bh[0], bh[2]);
                    MMA_BF16(acc[mt][nt1], ah[mt], bh[1], bh[3]);
                    MMA_BF16(acc[mt][nt1], ah[mt], bl[1], bl[3]);
                    MMA_BF16(acc[mt][nt1], al[mt], bh[1], bh[3]);
                }
            }
        }
        __syncthreads();
    }
}

// Fragment -> (row, col) mapping helpers:
// row = mw*32 + mt*16 + (lane>>2) + 8*h ; col = nw*64 + nt*8 + (lane&3)*2 + {0,1}
// acc element e = h*2 + {0,1}.

// ---------------- 0) converts ------------------------------------------------
__device__ __forceinline__ void split_store(float x, __nv_bfloat16* hi,
                                            __nv_bfloat16* lo, int i)
{
    __nv_bfloat16 h = __float2bfloat16(x);
    hi[i] = h;
    lo[i] = __float2bfloat16(x - __bfloat162float(h));
}

__global__ void convert_x_kernel(const float* __restrict__ src) {
    int i = blockIdx.x * 256 + threadIdx.x;
    if (i < BS_ * D_) split_store(src[i], g_Xhi, g_Xlo, i);
}
__global__ void convert_w_kernel(const float* __restrict__ src, int z) {
    int i = blockIdx.x * 256 + threadIdx.x;
    if (i < D_ * D_) split_store(src[i], g_Whi[z], g_Wlo[z], i);
}
__global__ void convert_r_kernel(const float* __restrict__ src, int h) {
    int i = blockIdx.x * 256 + threadIdx.x;
    if (i < NREL * D_) split_store(src[i], g_Rhi[h], g_Rlo[h], i);
}

// ---------------- 1) projections --------------------------------------------
__global__ void __launch_bounds__(256, 2)
proj_kernel(const float* __restrict__ bq1, const float* __restrict__ bk1,
            const float* __restrict__ bq2, const float* __restrict__ bk2)
{
    const int z = blockIdx.z;
    const float* bias = (z == 0) ? bq1 : (z == 1) ? bk1 : (z == 2) ? bq2 : bk2;
    const float scale = (z == 0 || z == 2) ? 0.0625f : 1.0f;

    const int mBase = blockIdx.y * 128;
    const int nBase = blockIdx.x * 128;

    float acc[2][8][4];
    gemm_mma(g_Xhi, g_Xlo, g_Whi[z], g_Wlo[z], mBase, nBase, 1 << 30, acc);

    const int lane = threadIdx.x & 31, wid = threadIdx.x >> 5;
    const int mw = wid >> 1, nw = wid & 1;

#pragma unroll
    for (int mt = 0; mt < 2; mt++) {
#pragma unroll
        for (int h = 0; h < 2; h++) {
            const int m = mBase + mw * 32 + mt * 16 + (lane >> 2) + 8 * h;
            __nv_bfloat16* dhi = g_Phi[z] + (size_t)m * D_;
            __nv_bfloat16* dlo = g_Plo[z] + (size_t)m * D_;
#pragma unroll
            for (int nt = 0; nt < 8; nt++) {
                const int col = nBase + nw * 64 + nt * 8 + (lane & 3) * 2;
                float y0 = (acc[mt][nt][h * 2 + 0] + bias[col + 0]) * scale;
                float y1 = (acc[mt][nt][h * 2 + 1] + bias[col + 1]) * scale;
                __nv_bfloat16 h0 = __float2bfloat16(y0);
                __nv_bfloat16 h1 = __float2bfloat16(y1);
                __nv_bfloat162 hp(h0, h1);
                __nv_bfloat162 lp(__float2bfloat16(y0 - __bfloat162float(h0)),
                                  __float2bfloat16(y1 - __bfloat162float(h1)));
                *(__nv_bfloat162*)(dhi + col) = hp;
                *(__nv_bfloat162*)(dlo + col) = lp;
            }
        }
    }
}

// ---------------- 2) q_rel ----------------------------------------------------
__global__ void __launch_bounds__(256, 2)
qr_kernel()
{
    const int head  = blockIdx.z;
    const int mBase = blockIdx.y * 128;
    const int nBase = blockIdx.x * 128;

    float acc[2][8][4];
    gemm_mma(g_Phi[head * 2], g_Plo[head * 2], g_Rhi[head], g_Rlo[head],
             mBase, nBase, NREL, acc);

    const int lane = threadIdx.x & 31, wid = threadIdx.x >> 5;
    const int mw = wid >> 1, nw = wid & 1;

#pragma unroll
    for (int mt = 0; mt < 2; mt++) {
#pragma unroll
        for (int h = 0; h < 2; h++) {
            const int m = mBase + mw * 32 + mt * 16 + (lane >> 2) + 8 * h;
            float* dst = g_QR[head] + (size_t)m * QRS;
#pragma unroll
            for (int nt = 0; nt < 8; nt++) {
                const int col = nBase + nw * 64 + nt * 8 + (lane & 3) * 2;
                if (col + 0 < NREL) dst[col + 0] = acc[mt][nt][h * 2 + 0];
                if (col + 1 < NREL) dst[col + 1] = acc[mt][nt][h * 2 + 1];
            }
        }
    }
}

// ---------------- 3) scores ---------------------------------------------------
__global__ void __launch_bounds__(256, 2)
scores_kernel(const int* __restrict__ mask, float* __restrict__ out)
{
    const int z    = blockIdx.z;
    const int head = z >> 3;
    const int b    = z & 7;
    const int qBase = blockIdx.y * 128;
    const int kBase = blockIdx.x * 128;

    const size_t po = (size_t)b * S_ * D_;
    float acc[2][8][4];
    gemm_mma(g_Phi[head * 2 + 0] + po, g_Plo[head * 2 + 0] + po,
             g_Phi[head * 2 + 1] + po, g_Plo[head * 2 + 1] + po,
             qBase, kBase, 1 << 30, acc);

    const int lane = threadIdx.x & 31, wid = threadIdx.x >> 5;
    const int mw = wid >> 1, nw = wid & 1;
    const int* mrow = mask + b * S_;

#pragma unroll
    for (int mt = 0; mt < 2; mt++) {
#pragma unroll
        for (int h = 0; h < 2; h++) {
            const int qg = qBase + mw * 32 + mt * 16 + (lane >> 2) + 8 * h;
            const int mq = mrow[qg];
            const float* qr = g_QR[head] + ((size_t)b * S_ + qg) * QRS;
            float* orow = out + (((size_t)head * B_ + b) * S_ + qg) * S_;
#pragma unroll
            for (int nt = 0; nt < 8; nt++) {
                const int kg = kBase + nw * 64 + nt * 8 + (lane & 3) * 2;
                int d0 = kg - qg;
                int d1 = d0 + 1;
                d0 = (d0 < -64) ? -64 : ((d0 > 64) ? 64 : d0);
                d1 = (d1 < -64) ? -64 : ((d1 > 64) ? 64 : d1);
                float v0 = acc[mt][nt][h * 2 + 0] + qr[d0 + 64];
                float v1 = acc[mt][nt][h * 2 + 1] + qr[d1 + 64];
                if (mq == 0 || mrow[kg + 0] == 0) v0 = -1e18f;
                if (mq == 0 || mrow[kg + 1] == 0) v1 = -1e18f;
                float2 v = make_float2(v0, v1);
                *(float2*)(orow + kg) = v;
            }
        }
    }
}

// ---------------- launch -------------------------------------------------------
extern "C" void kernel_launch(void* const* d_in, const int* in_sizes, int n_in,
                              void* d_out, int out_size)
{
    const float* repre = (const float*)d_in[0];
    const int*   mask  = (const int*)d_in[1];
    const float* wq1 = (const float*)d_in[2];
    const float* bq1 = (const float*)d_in[3];
    const float* wk1 = (const float*)d_in[4];
    const float* bk1 = (const float*)d_in[5];
    const float* rel1 = (const float*)d_in[6];
    const float* wq2 = (const float*)d_in[7];
    const float* bq2 = (const float*)d_in[8];
    const float* wk2 = (const float*)d_in[9];
    const float* bk2 = (const float*)d_in[10];
    const float* rel2 = (const float*)d_in[11];
    float* out = (float*)d_out;
    (void)in_sizes; (void)n_in; (void)out_size;

    static bool attr_set = false;
    cudaFuncSetAttribute(proj_kernel,
                         cudaFuncAttributeMaxDynamicSharedMemorySize, SMEM_DYN);
    cudaFuncSetAttribute(qr_kernel,
                         cudaFuncAttributeMaxDynamicSharedMemorySize, SMEM_DYN);
    cudaFuncSetAttribute(scores_kernel,
                         cudaFuncAttributeMaxDynamicSharedMemorySize, SMEM_DYN);
    (void)attr_set;

    const int NX = BS_ * D_;
    const int NW = D_ * D_;
    const int NR = NREL * D_;

    convert_x_kernel<<<(NX + 255) / 256, 256>>>(repre);
    convert_w_kernel<<<(NW + 255) / 256, 256>>>(wq1, 0);
    convert_w_kernel<<<(NW + 255) / 256, 256>>>(wk1, 1);
    convert_w_kernel<<<(NW + 255) / 256, 256>>>(wq2, 2);
    convert_w_kernel<<<(NW + 255) / 256, 256>>>(wk2, 3);
    convert_r_kernel<<<(NR + 255) / 256, 256>>>(rel1, 0);
    convert_r_kernel<<<(NR + 255) / 256, 256>>>(rel2, 1);

    proj_kernel<<<dim3(2, 128, 4), 256, SMEM_DYN>>>(bq1, bk1, bq2, bk2);
    qr_kernel<<<dim3(2, 128, 2), 256, SMEM_DYN>>>();
    scores_kernel<<<dim3(16, 16, 16), 256, SMEM_DYN>>>(mask, out);
}

// round 4
// speedup vs baseline: 2.3756x; 1.0031x over previous
#include <cuda_runtime.h>
#include <cuda_bf16.h>
#include <cstdint>

// ---------------------------------------------------------------------------
// SpanClassifier via portable mma.sync bf16x3 (split-fp32) GEMMs with a
// cp.async 2-stage pipelined mainloop.
//   B=8, S=2048, D=256, NREL=129
// Pipeline:
//   0) convert:  f32 -> (hi,lo) bf16 pairs for X (vectorized) and W1..4/rel1..2
//   1) proj:     Q1,K1,Q2,K2 = X@W^T + b (Q scaled 1/16) -> bf16 hi/lo
//   2) qr:       QR_h = Q_h @ rel_h^T -> f32 [16384,129] (stride 132)
//   3) scores:   out = Q@K^T + QR gather(clip(k-q)) + mask
// GEMM tile: 128x128, K=256 in 8 chunks of 32, 2-stage cp.async double buffer.
// Per k16-step: 3 MMAs (hi*hi, hi*lo, lo*hi), fp32 accumulate in registers.
// ---------------------------------------------------------------------------

namespace {
constexpr int B_   = 8;
constexpr int S_   = 2048;
constexpr int D_   = 256;
constexpr int NREL = 129;
constexpr int QRS  = 132;
constexpr int BS_  = B_ * S_;   // 16384

constexpr int KC    = 32;                 // k-chunk (bf16 elems)
constexpr int NCH   = D_ / KC;            // 8
constexpr int STRB  = 80;                 // smem row stride bytes (64 data + 16 pad)
constexpr int TILE_B = 128 * STRB;        // 10240 bytes
constexpr int STAGE_B = 4 * TILE_B;       // 40960 bytes (AHI,ALO,BHI,BLO)
constexpr int SMEM_DYN = 2 * STAGE_B;     // 81920 bytes
constexpr int T_AHI = 0;
constexpr int T_ALO = TILE_B;
constexpr int T_BHI = 2 * TILE_B;
constexpr int T_BLO = 3 * TILE_B;
}

// ---------------- scratch (device globals; no runtime allocation) ----------
__device__ __nv_bfloat16 g_Xhi[BS_ * D_];
__device__ __nv_bfloat16 g_Xlo[BS_ * D_];
__device__ __nv_bfloat16 g_Phi[4][BS_ * D_];
__device__ __nv_bfloat16 g_Plo[4][BS_ * D_];
__device__ __nv_bfloat16 g_Whi[4][D_ * D_];
__device__ __nv_bfloat16 g_Wlo[4][D_ * D_];
__device__ __nv_bfloat16 g_Rhi[2][NREL * D_];
__device__ __nv_bfloat16 g_Rlo[2][NREL * D_];
__device__ float g_QR[2][BS_ * QRS];

// ---------------- PTX helpers ----------------------------------------------
__device__ __forceinline__ uint32_t smem_u32(const void* p) {
    uint32_t a;
    asm("{ .reg .u64 t; cvta.to.shared.u64 t, %1; cvt.u32.u64 %0, t; }"
        : "=r"(a) : "l"(p));
    return a;
}

#define LDSM4(R, addr)                                                        \
    asm volatile("ldmatrix.sync.aligned.m8n8.x4.shared.b16 {%0,%1,%2,%3}, [%4];" \
                 : "=r"((R)[0]), "=r"((R)[1]), "=r"((R)[2]), "=r"((R)[3])     \
                 : "r"(addr))

#define MMA_BF16(C, A, B0, B1)                                                \
    asm volatile("mma.sync.aligned.m16n8k16.row.col.f32.bf16.bf16.f32 "       \
                 "{%0,%1,%2,%3},{%4,%5,%6,%7},{%8,%9},{%0,%1,%2,%3};"         \
                 : "+f"((C)[0]), "+f"((C)[1]), "+f"((C)[2]), "+f"((C)[3])     \
                 : "r"((A)[0]), "r"((A)[1]), "r"((A)[2]), "r"((A)[3]),        \
                   "r"(B0), "r"(B1))

__device__ __forceinline__ void cp16(uint32_t dst, const void* src, bool valid) {
    uint32_t n = valid ? 16u : 0u;
    asm volatile("cp.async.cg.shared.global [%0], [%1], 16, %2;"
                 :: "r"(dst), "l"(src), "r"(n));
}
#define CP_COMMIT() asm volatile("cp.async.commit_group;" ::: "memory")
#define CP_WAIT1()  asm volatile("cp.async.wait_group 1;" ::: "memory")
#define CP_WAIT0()  asm volatile("cp.async.wait_group 0;" ::: "memory")

// ---------------- stage prefetch: 4 tiles of [128 x 32] bf16 ---------------
// Each thread issues 8 cp.asyncs (2 per tile).
__device__ __forceinline__ void prefetch_stage(
    uint32_t smstage,
    const __nv_bfloat16* __restrict__ Ahi, const __nv_bfloat16* __restrict__ Alo,
    const __nv_bfloat16* __restrict__ Bhi, const __nv_bfloat16* __restrict__ Blo,
    int rowA0, int rowB0, int bLim, int col0, int tid)
{
#pragma unroll
    for (int t = 0; t < 2; t++) {
        const int idx = t * 256 + tid;     // 0..511
        const int r   = idx >> 2;          // 0..127
        const int c4  = idx & 3;           // 16B group
        const uint32_t so = (uint32_t)(r * STRB + c4 * 16);
        const size_t gao = (size_t)(rowA0 + r) * D_ + col0 + c4 * 8;
        cp16(smstage + T_AHI + so, Ahi + gao, true);
        cp16(smstage + T_ALO + so, Alo + gao, true);
        const bool bv = (rowB0 + r) < bLim;
        const int gbr = bv ? (rowB0 + r) : 0;
        const size_t gbo = (size_t)gbr * D_ + col0 + c4 * 8;
        cp16(smstage + T_BHI + so, Bhi + gbo, bv);
        cp16(smstage + T_BLO + so, Blo + gbo, bv);
    }
}

// ---------------- GEMM core: acc[2][8][4] = A[128,256] * B^T ---------------
// Warp grid 4x2 (m x n): warp computes 32x64 via 2x8 m16n8k16 tiles.
extern __shared__ char dynsm[];

__device__ __forceinline__ void gemm_mma(
    const __nv_bfloat16* __restrict__ Ahi, const __nv_bfloat16* __restrict__ Alo,
    const __nv_bfloat16* __restrict__ Bhi, const __nv_bfloat16* __restrict__ Blo,
    int rowA0, int rowB0, int bLim, float acc[2][8][4])
{
    const int tid  = threadIdx.x;
    const int lane = tid & 31;
    const int wid  = tid >> 5;
    const int mw   = wid >> 1;   // 0..3
    const int nw   = wid & 1;    // 0..1

    const uint32_t smb = smem_u32(dynsm);

    // ldmatrix lane addressing: row = lane&15 within 16-row group,
    // k-half byte offset = (lane>>4)*16.
    const int lrow       = lane & 15;
    const uint32_t khalf = (uint32_t)((lane >> 4) * 16);

    const uint32_t aOff = (uint32_t)((mw * 32 + lrow) * STRB) + khalf;
    const uint32_t bOff = (uint32_t)((nw * 64 + lrow) * STRB) + khalf;

#pragma unroll
    for (int mt = 0; mt < 2; mt++)
#pragma unroll
        for (int nt = 0; nt < 8; nt++)
#pragma unroll
            for (int e = 0; e < 4; e++) acc[mt][nt][e] = 0.f;

    // prologue: prefetch chunk 0 into stage 0
    prefetch_stage(smb, Ahi, Alo, Bhi, Blo, rowA0, rowB0, bLim, 0, tid);
    CP_COMMIT();

    for (int c = 0; c < NCH; c++) {
        if (c + 1 < NCH) {
            prefetch_stage(smb + ((c + 1) & 1) * STAGE_B, Ahi, Alo, Bhi, Blo,
                           rowA0, rowB0, bLim, (c + 1) * KC, tid);
            CP_COMMIT();
            CP_WAIT1();
        } else {
            CP_WAIT0();
        }
        __syncthreads();

        const uint32_t st = smb + (c & 1) * STAGE_B;
        const uint32_t aHi = st + T_AHI + aOff;
        const uint32_t aLo = st + T_ALO + aOff;
        const uint32_t bHi = st + T_BHI + bOff;
        const uint32_t bLo = st + T_BLO + bOff;

#pragma unroll
        for (int ks = 0; ks < 2; ks++) {
            const uint32_t ko = (uint32_t)(ks * 32);
            uint32_t ah[2][4], al[2][4];
#pragma unroll
            for (int mt = 0; mt < 2; mt++) {
                LDSM4(ah[mt], aHi + (uint32_t)(mt * 16 * STRB) + ko);
                LDSM4(al[mt], aLo + (uint32_t)(mt * 16 * STRB) + ko);
            }
#pragma unroll
            for (int ntp = 0; ntp < 4; ntp++) {
                uint32_t bh[4], bl[4];
                LDSM4(bh, bHi + (uint32_t)(ntp * 16 * STRB) + ko);
                LDSM4(bl, bLo + (uint32_t)(ntp * 16 * STRB) + ko);
                const int nt0 = ntp * 2, nt1 = nt0 + 1;
#pragma unroll
                for (int mt = 0; mt < 2; mt++) {
                    MMA_BF16(acc[mt][nt0], ah[mt], bh[0], bh[2]);
                    MMA_BF16(acc[mt][nt0], ah[mt], bl[0], bl[2]);
                    MMA_BF16(acc[mt][nt0], al[mt], bh[0], bh[2]);
                    MMA_BF16(acc[mt][nt1], ah[mt], bh[1], bh[3]);
                    MMA_BF16(acc[mt][nt1], ah[mt], bl[1], bl[3]);
                    MMA_BF16(acc[mt][nt1], al[mt], bh[1], bh[3]);
                }
            }
        }
        __syncthreads();
    }
}

// Fragment -> (row, col): row = mw*32 + mt*16 + (lane>>2) + 8*h ;
// col = nw*64 + nt*8 + (lane&3)*2 + {0,1} ; acc element e = h*2 + {0,1}.

// ---------------- 0) converts ------------------------------------------------
__device__ __forceinline__ void split_store(float x, __nv_bfloat16* hi,
                                            __nv_bfloat16* lo, size_t i)
{
    __nv_bfloat16 h = __float2bfloat16(x);
    hi[i] = h;
    lo[i] = __float2bfloat16(x - __bfloat162float(h));
}

__global__ void convert_x_kernel(const float* __restrict__ src) {
    const int i4 = blockIdx.x * 256 + threadIdx.x;
    const size_t i = (size_t)i4 * 4;
    if (i + 3 < (size_t)BS_ * D_) {
        float4 v = *(const float4*)(src + i);
        __nv_bfloat16 h0 = __float2bfloat16(v.x), h1 = __float2bfloat16(v.y);
        __nv_bfloat16 h2 = __float2bfloat16(v.z), h3 = __float2bfloat16(v.w);
        __nv_bfloat162 hp0(h0, h1), hp1(h2, h3);
        __nv_bfloat162 lp0(__float2bfloat16(v.x - __bfloat162float(h0)),
                           __float2bfloat16(v.y - __bfloat162float(h1)));
        __nv_bfloat162 lp1(__float2bfloat16(v.z - __bfloat162float(h2)),
                           __float2bfloat16(v.w - __bfloat162float(h3)));
        *(__nv_bfloat162*)(g_Xhi + i)     = hp0;
        *(__nv_bfloat162*)(g_Xhi + i + 2) = hp1;
        *(__nv_bfloat162*)(g_Xlo + i)     = lp0;
        *(__nv_bfloat162*)(g_Xlo + i + 2) = lp1;
    }
}

// One launch for all 4 weights + 2 rel tables. blockIdx.y selects source.
__global__ void convert_small_kernel(
    const float* __restrict__ w0, const float* __restrict__ w1,
    const float* __restrict__ w2, const float* __restrict__ w3,
    const float* __restrict__ r0, const float* __restrict__ r1)
{
    const int z = blockIdx.y;
    const float* src;
    __nv_bfloat16 *hi, *lo;
    int n;
    if (z < 4) {
        src = (z == 0) ? w0 : (z == 1) ? w1 : (z == 2) ? w2 : w3;
        hi = g_Whi[z]; lo = g_Wlo[z]; n = D_ * D_;
    } else {
        src = (z == 4) ? r0 : r1;
        hi = g_Rhi[z - 4]; lo = g_Rlo[z - 4]; n = NREL * D_;
    }
    int i = blockIdx.x * 256 + threadIdx.x;
    if (i < n) split_store(src[i], hi, lo, i);
}

// ---------------- 1) projections --------------------------------------------
__global__ void __launch_bounds__(256, 2)
proj_kernel(const float* __restrict__ bq1, const float* __restrict__ bk1,
            const float* __restrict__ bq2, const float* __restrict__ bk2)
{
    const int z = blockIdx.z;
    const float* bias = (z == 0) ? bq1 : (z == 1) ? bk1 : (z == 2) ? bq2 : bk2;
    const float scale = (z == 0 || z == 2) ? 0.0625f : 1.0f;

    const int mBase = blockIdx.y * 128;
    const int nBase = blockIdx.x * 128;

    float acc[2][8][4];
    gemm_mma(g_Xhi, g_Xlo, g_Whi[z], g_Wlo[z], mBase, nBase, 1 << 30, acc);

    const int lane = threadIdx.x & 31, wid = threadIdx.x >> 5;
    const int mw = wid >> 1, nw = wid & 1;

#pragma unroll
    for (int mt = 0; mt < 2; mt++) {
#pragma unroll
        for (int h = 0; h < 2; h++) {
            const int m = mBase + mw * 32 + mt * 16 + (lane >> 2) + 8 * h;
            __nv_bfloat16* dhi = g_Phi[z] + (size_t)m * D_;
            __nv_bfloat16* dlo = g_Plo[z] + (size_t)m * D_;
#pragma unroll
            for (int nt = 0; nt < 8; nt++) {
                const int col = nBase + nw * 64 + nt * 8 + (lane & 3) * 2;
                float y0 = (acc[mt][nt][h * 2 + 0] + bias[col + 0]) * scale;
                float y1 = (acc[mt][nt][h * 2 + 1] + bias[col + 1]) * scale;
                __nv_bfloat16 h0 = __float2bfloat16(y0);
                __nv_bfloat16 h1 = __float2bfloat16(y1);
                __nv_bfloat162 hp(h0, h1);
                __nv_bfloat162 lp(__float2bfloat16(y0 - __bfloat162float(h0)),
                                  __float2bfloat16(y1 - __bfloat162float(h1)));
                *(__nv_bfloat162*)(dhi + col) = hp;
                *(__nv_bfloat162*)(dlo + col) = lp;
            }
        }
    }
}

// ---------------- 2) q_rel ----------------------------------------------------
__global__ void __launch_bounds__(256, 2)
qr_kernel()
{
    const int head  = blockIdx.z;
    const int mBase = blockIdx.y * 128;
    const int nBase = blockIdx.x * 128;

    float acc[2][8][4];
    gemm_mma(g_Phi[head * 2], g_Plo[head * 2], g_Rhi[head], g_Rlo[head],
             mBase, nBase, NREL, acc);

    const int lane = threadIdx.x & 31, wid = threadIdx.x >> 5;
    const int mw = wid >> 1, nw = wid & 1;

#pragma unroll
    for (int mt = 0; mt < 2; mt++) {
#pragma unroll
        for (int h = 0; h < 2; h++) {
            const int m = mBase + mw * 32 + mt * 16 + (lane >> 2) + 8 * h;
            float* dst = g_QR[head] + (size_t)m * QRS;
#pragma unroll
            for (int nt = 0; nt < 8; nt++) {
                const int col = nBase + nw * 64 + nt * 8 + (lane & 3) * 2;
                if (col + 0 < NREL) dst[col + 0] = acc[mt][nt][h * 2 + 0];
                if (col + 1 < NREL) dst[col + 1] = acc[mt][nt][h * 2 + 1];
            }
        }
    }
}

// ---------------- 3) scores ---------------------------------------------------
__global__ void __launch_bounds__(256, 2)
scores_kernel(const int* __restrict__ mask, float* __restrict__ out)
{
    const int z    = blockIdx.z;
    const int head = z >> 3;
    const int b    = z & 7;
    const int qBase = blockIdx.y * 128;
    const int kBase = blockIdx.x * 128;

    const size_t po = (size_t)b * S_ * D_;
    float acc[2][8][4];
    gemm_mma(g_Phi[head * 2 + 0] + po, g_Plo[head * 2 + 0] + po,
             g_Phi[head * 2 + 1] + po, g_Plo[head * 2 + 1] + po,
             qBase, kBase, 1 << 30, acc);

    const int lane = threadIdx.x & 31, wid = threadIdx.x >> 5;
    const int mw = wid >> 1, nw = wid & 1;
    const int* mrow = mask + b * S_;

#pragma unroll
    for (int mt = 0; mt < 2; mt++) {
#pragma unroll
        for (int h = 0; h < 2; h++) {
            const int qg = qBase + mw * 32 + mt * 16 + (lane >> 2) + 8 * h;
            const int mq = mrow[qg];
            const float* qr = g_QR[head] + ((size_t)b * S_ + qg) * QRS;
            float* orow = out + (((size_t)head * B_ + b) * S_ + qg) * S_;
#pragma unroll
            for (int nt = 0; nt < 8; nt++) {
                const int kg = kBase + nw * 64 + nt * 8 + (lane & 3) * 2;
                int d0 = kg - qg;
                int d1 = d0 + 1;
                d0 = (d0 < -64) ? -64 : ((d0 > 64) ? 64 : d0);
                d1 = (d1 < -64) ? -64 : ((d1 > 64) ? 64 : d1);
                float v0 = acc[mt][nt][h * 2 + 0] + qr[d0 + 64];
                float v1 = acc[mt][nt][h * 2 + 1] + qr[d1 + 64];
                if (mq == 0 || mrow[kg + 0] == 0) v0 = -1e18f;
                if (mq == 0 || mrow[kg + 1] == 0) v1 = -1e18f;
                float2 v = make_float2(v0, v1);
                *(float2*)(orow + kg) = v;
            }
        }
    }
}

// ---------------- launch -------------------------------------------------------
extern "C" void kernel_launch(void* const* d_in, const int* in_sizes, int n_in,
                              void* d_out, int out_size)
{
    const float* repre = (const float*)d_in[0];
    const int*   mask  = (const int*)d_in[1];
    const float* wq1 = (const float*)d_in[2];
    const float* bq1 = (const float*)d_in[3];
    const float* wk1 = (const float*)d_in[4];
    const float* bk1 = (const float*)d_in[5];
    const float* rel1 = (const float*)d_in[6];
    const float* wq2 = (const float*)d_in[7];
    const float* bq2 = (const float*)d_in[8];
    const float* wk2 = (const float*)d_in[9];
    const float* bk2 = (const float*)d_in[10];
    const float* rel2 = (const float*)d_in[11];
    float* out = (float*)d_out;
    (void)in_sizes; (void)n_in; (void)out_size;

    cudaFuncSetAttribute(proj_kernel,
                         cudaFuncAttributeMaxDynamicSharedMemorySize, SMEM_DYN);
    cudaFuncSetAttribute(qr_kernel,
                         cudaFuncAttributeMaxDynamicSharedMemorySize, SMEM_DYN);
    cudaFuncSetAttribute(scores_kernel,
                         cudaFuncAttributeMaxDynamicSharedMemorySize, SMEM_DYN);

    const int NX4 = BS_ * D_ / 4;
    const int NW = D_ * D_;

    convert_x_kernel<<<(NX4 + 255) / 256, 256>>>(repre);
    convert_small_kernel<<<dim3((NW + 255) / 256, 6), 256>>>(
        wq1, wk1, wq2, wk2, rel1, rel2);

    proj_kernel<<<dim3(2, 128, 4), 256, SMEM_DYN>>>(bq1, bk1, bq2, bk2);
    qr_kernel<<<dim3(2, 128, 2), 256, SMEM_DYN>>>();
    scores_kernel<<<dim3(16, 16, 16), 256, SMEM_DYN>>>(mask, out);
}